// round 1
// baseline (speedup 1.0000x reference)
#include <cuda_runtime.h>

// ---------------------------------------------------------------------------
// SphericalLinear: per-point filter routing + grouped linear.
// Strategy: classify -> bucket-count -> aligned offsets -> scatter permutation
//           -> per-tile uniform-filter GEMM (128x128x256) on CUDA cores using
//           packed fp32x2 FMA (sm_103a FFMA2 via PTX fma.rn.f32x2).
// ---------------------------------------------------------------------------

#define NFILT   4
#define C_IN    256
#define C_OUT   512
#define TILE_M  128
#define TILE_N  128
#define KC      32
#define LDA     36      // sA row stride in floats (float4-aligned, conflict-free)
#define LDB     131     // sB row stride in floats (prime-ish: conflict-free STS/LDS)
#define MAXP    65536

// Scratch (allocation-free rule: device globals)
__device__ int d_filt[MAXP];
__device__ int d_perm[MAXP + NFILT * TILE_M];
__device__ int d_count[NFILT];
__device__ int d_fill[NFILT];
__device__ int d_start[NFILT + 1];

// ---- packed fp32x2 helpers -------------------------------------------------
__device__ __forceinline__ unsigned long long pack2(float lo, float hi) {
    unsigned long long r;
    asm("mov.b64 %0, {%1, %2};" : "=l"(r) : "f"(lo), "f"(hi));
    return r;
}
__device__ __forceinline__ void unpack2(unsigned long long v, float& lo, float& hi) {
    asm("mov.b64 {%0, %1}, %2;" : "=f"(lo), "=f"(hi) : "l"(v));
}
__device__ __forceinline__ void fma2(unsigned long long& d,
                                     unsigned long long a,
                                     unsigned long long b) {
    asm("fma.rn.f32x2 %0, %1, %2, %3;" : "=l"(d) : "l"(a), "l"(b), "l"(d));
}

// ---- k0: reset counters ----------------------------------------------------
__global__ void reset_kernel() {
    int t = threadIdx.x;
    if (t < NFILT) { d_count[t] = 0; d_fill[t] = 0; }
}

// ---- k1: classify + histogram ---------------------------------------------
__global__ void classify_kernel(const float* __restrict__ xyz, int P) {
    __shared__ int sc[NFILT];
    int tid = threadIdx.x;
    if (tid < NFILT) sc[tid] = 0;
    __syncthreads();

    int p = blockIdx.x * blockDim.x + tid;
    if (p < P) {
        float x = xyz[3 * p + 0];
        float y = xyz[3 * p + 1];
        float z = xyz[3 * p + 2];
        float r = sqrtf(x * x + y * y + z * z);
        int f;
        if      (r < 1.0f)   f = 0;
        else if (r < 1.5f)   f = 1;
        else if (r < 2.0f)   f = 2;
        else if (r < 100.0f) f = 3;
        else                 f = 0;   // argmax of all-False -> 0 (matches jnp)
        d_filt[p] = f;
        atomicAdd(&sc[f], 1);
    }
    __syncthreads();
    if (tid < NFILT && sc[tid] != 0) atomicAdd(&d_count[tid], sc[tid]);
}

// ---- k2: aligned bucket starts --------------------------------------------
__global__ void offsets_kernel() {
    if (threadIdx.x == 0 && blockIdx.x == 0) {
        int s = 0;
        #pragma unroll
        for (int f = 0; f < NFILT; f++) {
            d_start[f] = s;
            s += ((d_count[f] + TILE_M - 1) / TILE_M) * TILE_M;
        }
        d_start[NFILT] = s;
    }
}

// ---- k3: scatter permutation (block-aggregated atomics) --------------------
__global__ void scatter_kernel(int P) {
    __shared__ int sc[NFILT];
    __shared__ int sbase[NFILT];
    int tid = threadIdx.x;
    if (tid < NFILT) sc[tid] = 0;
    __syncthreads();

    int p = blockIdx.x * blockDim.x + tid;
    int f = 0, rank = 0;
    if (p < P) {
        f = d_filt[p];
        rank = atomicAdd(&sc[f], 1);
    }
    __syncthreads();
    if (tid < NFILT) sbase[tid] = (sc[tid] != 0) ? atomicAdd(&d_fill[tid], sc[tid]) : 0;
    __syncthreads();
    if (p < P) d_perm[d_start[f] + sbase[f] + rank] = p;
}

// ---- k4: uniform-filter GEMM tile ------------------------------------------
// CTA: 256 threads = 16(ty) x 16(tx). Microtile: rows m = ty + 16*i (i<8),
// cols n = tx + 16*j (j<8). Interleaved mapping -> conflict-free LDS.
__global__ void __launch_bounds__(256, 2)
gemm_kernel(const float* __restrict__ feat,
            const float* __restrict__ weight,
            const float* __restrict__ bias,
            float* __restrict__ out) {
    __shared__ float sA[TILE_M][LDA];   // [m][k], k-chunk of 32
    __shared__ float sB[KC][LDB];       // [k][n]
    __shared__ int   sPerm[TILE_M];

    const int tid = threadIdx.x;
    const int rowbase = blockIdx.x * TILE_M;

    const int total = d_start[NFILT];
    if (rowbase >= total) return;

    int f = NFILT - 1;
    #pragma unroll
    for (int ff = NFILT - 1; ff >= 0; ff--)
        if (rowbase < d_start[ff + 1]) f = ff;

    int nval = d_start[f] + d_count[f] - rowbase;
    if (nval <= 0) return;            // tile entirely in the padding region
    if (nval > TILE_M) nval = TILE_M;

    if (tid < TILE_M) {
        sPerm[tid] = (tid < nval) ? d_perm[rowbase + tid] : d_perm[rowbase];
    }
    __syncthreads();

    const float* wbase = weight + ((size_t)f * C_OUT + blockIdx.y * TILE_N) * C_IN;

    unsigned long long acc[32];       // [i][jj] : i*4 + jj ; pair (n=tx+32jj, n=tx+32jj+16)
    #pragma unroll
    for (int i = 0; i < 32; i++) acc[i] = 0ull;

    const int ty = tid >> 4;
    const int tx = tid & 15;
    const int lm = tid >> 3;           // 0..31
    const int lc = (tid & 7) * 4;      // 0,4,...,28

    #pragma unroll 1
    for (int kt = 0; kt < C_IN; kt += KC) {
        // load A: gathered feat rows -> sA[m][k] (direct, float4, conflict-free)
        #pragma unroll
        for (int it = 0; it < 4; it++) {
            int m = lm + 32 * it;
            const float4 v = *(const float4*)(feat + (size_t)sPerm[m] * C_IN + kt + lc);
            *(float4*)&sA[m][lc] = v;
        }
        // load B: weight rows (O,C) transposed -> sB[k][n] (LDB=131: conflict-free STS)
        #pragma unroll
        for (int it = 0; it < 4; it++) {
            int n = lm + 32 * it;
            const float4 v = *(const float4*)(wbase + (size_t)n * C_IN + kt + lc);
            sB[lc + 0][n] = v.x;
            sB[lc + 1][n] = v.y;
            sB[lc + 2][n] = v.z;
            sB[lc + 3][n] = v.w;
        }
        __syncthreads();

        #pragma unroll 4
        for (int k = 0; k < KC; k++) {
            float a[8], b[8];
            #pragma unroll
            for (int i = 0; i < 8; i++) a[i] = sA[ty + 16 * i][k];   // 2-addr broadcast
            #pragma unroll
            for (int j = 0; j < 8; j++) b[j] = sB[k][tx + 16 * j];   // consecutive banks

            unsigned long long bp[4];
            #pragma unroll
            for (int jj = 0; jj < 4; jj++) bp[jj] = pack2(b[2 * jj], b[2 * jj + 1]);

            #pragma unroll
            for (int i = 0; i < 8; i++) {
                unsigned long long ap = pack2(a[i], a[i]);
                #pragma unroll
                for (int jj = 0; jj < 4; jj++) fma2(acc[i * 4 + jj], ap, bp[jj]);
            }
        }
        __syncthreads();
    }

    // epilogue: add bias, scatter rows back
    const float* bbase = bias + (size_t)f * C_OUT + blockIdx.y * TILE_N;
    #pragma unroll
    for (int i = 0; i < 8; i++) {
        int m = ty + 16 * i;
        if (m < nval) {
            float* orow = out + (size_t)sPerm[m] * C_OUT + blockIdx.y * TILE_N;
            #pragma unroll
            for (int jj = 0; jj < 4; jj++) {
                float lo, hi;
                unpack2(acc[i * 4 + jj], lo, hi);
                int n0 = tx + 32 * jj;
                orow[n0]      = lo + bbase[n0];
                orow[n0 + 16] = hi + bbase[n0 + 16];
            }
        }
    }
}

// ---------------------------------------------------------------------------
extern "C" void kernel_launch(void* const* d_in, const int* in_sizes, int n_in,
                              void* d_out, int out_size) {
    const float* feat   = (const float*)d_in[0];
    const float* xyz    = (const float*)d_in[1];
    const float* weight = (const float*)d_in[2];
    const float* bias   = (const float*)d_in[3];
    float* out = (float*)d_out;

    const int P = in_sizes[0] / C_IN;

    reset_kernel<<<1, 32>>>();
    classify_kernel<<<(P + 255) / 256, 256>>>(xyz, P);
    offsets_kernel<<<1, 32>>>();
    scatter_kernel<<<(P + 255) / 256, 256>>>(P);

    const int mtiles = (P + TILE_M - 1) / TILE_M + NFILT;  // + padding slack
    dim3 grid(mtiles, C_OUT / TILE_N);
    gemm_kernel<<<grid, 256>>>(feat, weight, bias, out);
}

// round 3
// speedup vs baseline: 2.3503x; 2.3503x over previous
#include <cuda_runtime.h>
#include <cuda_bf16.h>
#include <cstdint>

// ---------------------------------------------------------------------------
// SphericalLinear on GB300 (PTX target sm_103 plain: no tcgen05 available).
// classify -> bucketed permutation -> pack fp32->bf16 hi/lo scratch (permuted)
// -> mma.sync bf16 3-split GEMM (AhBh + AhBl + AlBh, fp32 accum)
// CTA tile 128x128, 8 warps 64x32, KC=32, 2-stage cp.async pipeline.
// ---------------------------------------------------------------------------

#define NFILT   4
#define C_IN    256
#define C_OUT   512
#define TILE_M  128
#define TILE_N  128
#define KC      32
#define NCHUNKS (C_IN / KC)          // 8
#define MAXP    65536
#define PADROWS (MAXP + NFILT * TILE_M)
#define THREADS 256

// SMEM tile geometry: bf16 rows of 32 elems (64B data) padded to 80B stride.
#define RS      80                    // row stride bytes (conflict-free ldmatrix)
#define MAT_SZ  (TILE_M * RS)         // 10240 bytes per matrix (A or B, hi or lo)
#define STAGE_SZ (4 * MAT_SZ)         // Ah, Al, Bh, Bl
#define SM_PERM  0
#define SM_TILE  1024
#define SMEM_TOTAL (SM_TILE + 2 * STAGE_SZ)

// ---- device scratch --------------------------------------------------------
__device__ int d_filt[MAXP];
__device__ int d_perm[PADROWS];
__device__ int d_count[NFILT];
__device__ int d_fill[NFILT];
__device__ int d_start[NFILT + 1];
__device__ __nv_bfloat16 d_Ahi[(size_t)PADROWS * C_IN];
__device__ __nv_bfloat16 d_Alo[(size_t)PADROWS * C_IN];
__device__ __nv_bfloat16 d_Whi[(size_t)NFILT * C_OUT * C_IN];
__device__ __nv_bfloat16 d_Wlo[(size_t)NFILT * C_OUT * C_IN];

// ---- helpers ---------------------------------------------------------------
__device__ __forceinline__ uint32_t smem_u32(const void* p) {
    uint32_t a;
    asm("{ .reg .u64 t; cvta.to.shared.u64 t, %1; cvt.u32.u64 %0, t; }" : "=r"(a) : "l"(p));
    return a;
}
__device__ __forceinline__ void cp16(uint32_t dst, const void* src) {
    asm volatile("cp.async.cg.shared.global [%0], [%1], 16;" :: "r"(dst), "l"(src) : "memory");
}
#define CP_COMMIT() asm volatile("cp.async.commit_group;" ::: "memory")
#define CP_WAIT1()  asm volatile("cp.async.wait_group 1;" ::: "memory")
#define CP_WAIT0()  asm volatile("cp.async.wait_group 0;" ::: "memory")

__device__ __forceinline__ void ldsm4(uint32_t* r, uint32_t addr) {
    asm volatile("ldmatrix.sync.aligned.m8n8.x4.shared.b16 {%0,%1,%2,%3}, [%4];"
                 : "=r"(r[0]), "=r"(r[1]), "=r"(r[2]), "=r"(r[3]) : "r"(addr));
}
__device__ __forceinline__ void mma_bf16(float* c, const uint32_t* a,
                                         uint32_t b0, uint32_t b1) {
    asm volatile("mma.sync.aligned.m16n8k16.row.col.f32.bf16.bf16.f32 "
                 "{%0,%1,%2,%3}, {%4,%5,%6,%7}, {%8,%9}, {%0,%1,%2,%3};"
                 : "+f"(c[0]), "+f"(c[1]), "+f"(c[2]), "+f"(c[3])
                 : "r"(a[0]), "r"(a[1]), "r"(a[2]), "r"(a[3]), "r"(b0), "r"(b1));
}

// fp32 -> (bf16 hi, bf16 lo) packed pairs
__device__ __forceinline__ void cvt_split2(float a0, float a1, uint32_t& hi, uint32_t& lo) {
    uint32_t p;
    asm("cvt.rn.bf16x2.f32 %0, %1, %2;" : "=r"(p) : "f"(a1), "f"(a0));
    float h0 = __uint_as_float(p << 16);
    float h1 = __uint_as_float(p & 0xFFFF0000u);
    float r0 = a0 - h0;
    float r1 = a1 - h1;
    uint32_t q;
    asm("cvt.rn.bf16x2.f32 %0, %1, %2;" : "=r"(q) : "f"(r1), "f"(r0));
    hi = p; lo = q;
}
__device__ __forceinline__ void cvt_split8(float4 v0, float4 v1, uint4& hi, uint4& lo) {
    cvt_split2(v0.x, v0.y, hi.x, lo.x);
    cvt_split2(v0.z, v0.w, hi.y, lo.y);
    cvt_split2(v1.x, v1.y, hi.z, lo.z);
    cvt_split2(v1.z, v1.w, hi.w, lo.w);
}

// ---- pipeline kernels ------------------------------------------------------
__global__ void reset_kernel() {
    int t = threadIdx.x;
    if (t < NFILT) { d_count[t] = 0; d_fill[t] = 0; }
}

__global__ void classify_kernel(const float* __restrict__ xyz, int P) {
    __shared__ int sc[NFILT];
    int tid = threadIdx.x;
    if (tid < NFILT) sc[tid] = 0;
    __syncthreads();
    int p = blockIdx.x * blockDim.x + tid;
    if (p < P) {
        float x = xyz[3 * p + 0], y = xyz[3 * p + 1], z = xyz[3 * p + 2];
        float r = sqrtf(x * x + y * y + z * z);
        int f;
        if      (r < 1.0f)   f = 0;
        else if (r < 1.5f)   f = 1;
        else if (r < 2.0f)   f = 2;
        else if (r < 100.0f) f = 3;
        else                 f = 0;
        d_filt[p] = f;
        atomicAdd(&sc[f], 1);
    }
    __syncthreads();
    if (tid < NFILT && sc[tid] != 0) atomicAdd(&d_count[tid], sc[tid]);
}

__global__ void offsets_kernel() {
    if (threadIdx.x == 0 && blockIdx.x == 0) {
        int s = 0;
        #pragma unroll
        for (int f = 0; f < NFILT; f++) {
            d_start[f] = s;
            s += ((d_count[f] + TILE_M - 1) / TILE_M) * TILE_M;
        }
        d_start[NFILT] = s;
    }
}

__global__ void scatter_kernel(int P) {
    __shared__ int sc[NFILT];
    __shared__ int sbase[NFILT];
    int tid = threadIdx.x;
    if (tid < NFILT) sc[tid] = 0;
    __syncthreads();
    int p = blockIdx.x * blockDim.x + tid;
    int f = 0, rank = 0;
    if (p < P) {
        f = d_filt[p];
        rank = atomicAdd(&sc[f], 1);
    }
    __syncthreads();
    if (tid < NFILT) sbase[tid] = (sc[tid] != 0) ? atomicAdd(&d_fill[tid], sc[tid]) : 0;
    __syncthreads();
    if (p < P) d_perm[d_start[f] + sbase[f] + rank] = p;
}

// pack feat through the permutation: scratch row q holds feat[perm[q]] as hi/lo
__global__ void pack_feat_kernel(const float* __restrict__ feat) {
    int tid = threadIdx.x;
    int q = blockIdx.x * 8 + (tid >> 5);
    int col = (tid & 31) * 8;
    if (q >= d_start[NFILT]) return;
    int f = 0;
    #pragma unroll
    for (int ff = 1; ff < NFILT; ff++)
        if (q >= d_start[ff]) f = ff;
    uint4 hi = {0, 0, 0, 0}, lo = {0, 0, 0, 0};
    if (q < d_start[f] + d_count[f]) {
        int p = d_perm[q];
        const float4* src = (const float4*)(feat + (size_t)p * C_IN + col);
        cvt_split8(src[0], src[1], hi, lo);
    }
    *(uint4*)(d_Ahi + (size_t)q * C_IN + col) = hi;
    *(uint4*)(d_Alo + (size_t)q * C_IN + col) = lo;
}

__global__ void pack_weight_kernel(const float* __restrict__ weight) {
    int tid = threadIdx.x;
    int q = blockIdx.x * 8 + (tid >> 5);           // 0 .. NFILT*C_OUT-1
    int col = (tid & 31) * 8;
    const float4* src = (const float4*)(weight + (size_t)q * C_IN + col);
    uint4 hi, lo;
    cvt_split8(src[0], src[1], hi, lo);
    *(uint4*)(d_Whi + (size_t)q * C_IN + col) = hi;
    *(uint4*)(d_Wlo + (size_t)q * C_IN + col) = lo;
}

// ---- GEMM ------------------------------------------------------------------
__global__ void __launch_bounds__(THREADS)
gemm_mma_kernel(const float* __restrict__ bias, float* __restrict__ out) {
    extern __shared__ char smem[];
    const int tid = threadIdx.x;
    const int lane = tid & 31;
    const int wid = tid >> 5;
    const int wm = wid >> 2;          // 0..1
    const int wn = wid & 3;           // 0..3
    const int by = blockIdx.y;

    const int rowbase = blockIdx.x * TILE_M;
    const int total = d_start[NFILT];
    if (rowbase >= total) return;

    int f = 0;
    #pragma unroll
    for (int ff = 1; ff < NFILT; ff++)
        if (rowbase >= d_start[ff]) f = ff;
    int nval = d_start[f] + d_count[f] - rowbase;
    if (nval <= 0) return;
    if (nval > TILE_M) nval = TILE_M;

    int* sPerm = (int*)(smem + SM_PERM);
    if (tid < TILE_M) sPerm[tid] = d_perm[rowbase + tid];

    const uint32_t sb = smem_u32(smem) + SM_TILE;

    // ---- cp.async stage loader: 4 matrices x 128 rows x 4 segs of 16B ----
    const char* srcA_h = (const char*)(d_Ahi + (size_t)rowbase * C_IN);
    const char* srcA_l = (const char*)(d_Alo + (size_t)rowbase * C_IN);
    const size_t wrow = ((size_t)f * C_OUT + (size_t)by * TILE_N) * C_IN;
    const char* srcB_h = (const char*)(d_Whi + wrow);
    const char* srcB_l = (const char*)(d_Wlo + wrow);

    auto load_stage = [&](int c, int s) {
        const int ktB = c * KC * 2;                 // byte offset into 512B rows
        const uint32_t base = sb + s * STAGE_SZ;
        #pragma unroll
        for (int it = 0; it < 2; it++) {
            int idx = it * THREADS + tid;           // 0..511
            int r = idx >> 2;
            int sg = (idx & 3) * 16;
            uint32_t d0 = base + r * RS + sg;
            size_t   so = (size_t)r * 512 + ktB + sg;
            cp16(d0 + 0 * MAT_SZ, srcA_h + so);
            cp16(d0 + 1 * MAT_SZ, srcA_l + so);
            cp16(d0 + 2 * MAT_SZ, srcB_h + so);
            cp16(d0 + 3 * MAT_SZ, srcB_l + so);
        }
        CP_COMMIT();
    };

    load_stage(0, 0);
    load_stage(1, 1);

    // ---- ldmatrix lane address components ----
    const int rA = ((lane >> 3) & 1) * 8 + (lane & 7);   // row within m16 tile
    const int kA = (lane >> 4);                          // k seg (0/1)
    const int rB = ((lane >> 4)) * 8 + (lane & 7);       // row within n16 tile
    const int kB = ((lane >> 3) & 1);

    float acc[4][4][4];
    #pragma unroll
    for (int i = 0; i < 4; i++)
        #pragma unroll
        for (int j = 0; j < 4; j++)
            #pragma unroll
            for (int e = 0; e < 4; e++) acc[i][j][e] = 0.0f;

    #pragma unroll 1
    for (int c = 0; c < NCHUNKS; c++) {
        const int s = c & 1;
        const uint32_t base = sb + s * STAGE_SZ;
        CP_WAIT1();
        __syncthreads();

        #pragma unroll
        for (int k16 = 0; k16 < 2; k16++) {
            const int kseg = k16 * 2;
            uint32_t ah[4][4], al[4][4];
            uint32_t bh[2][4], bl[2][4];
            #pragma unroll
            for (int mi = 0; mi < 4; mi++) {
                uint32_t ad = base + (wm * 64 + mi * 16 + rA) * RS + (kseg + kA) * 16;
                ldsm4(ah[mi], ad + 0 * MAT_SZ);
                ldsm4(al[mi], ad + 1 * MAT_SZ);
            }
            #pragma unroll
            for (int nj = 0; nj < 2; nj++) {
                uint32_t bd = base + (wn * 32 + nj * 16 + rB) * RS + (kseg + kB) * 16;
                ldsm4(bh[nj], bd + 2 * MAT_SZ);
                ldsm4(bl[nj], bd + 3 * MAT_SZ);
            }
            #pragma unroll
            for (int mi = 0; mi < 4; mi++) {
                #pragma unroll
                for (int n8 = 0; n8 < 4; n8++) {
                    const int nj = n8 >> 1, h = (n8 & 1) * 2;
                    mma_bf16(acc[mi][n8], ah[mi], bh[nj][h], bh[nj][h + 1]);
                    mma_bf16(acc[mi][n8], ah[mi], bl[nj][h], bl[nj][h + 1]);
                    mma_bf16(acc[mi][n8], al[mi], bh[nj][h], bh[nj][h + 1]);
                }
            }
        }
        __syncthreads();
        if (c + 2 < NCHUNKS) load_stage(c + 2, s);
    }

    // ---- epilogue: bias + scattered stores ----
    const int g = lane >> 2;
    const int a2 = (lane & 3) * 2;
    float2 bv[4];
    #pragma unroll
    for (int ni = 0; ni < 4; ni++)
        bv[ni] = *(const float2*)(bias + (size_t)f * C_OUT + by * TILE_N + wn * 32 + ni * 8 + a2);

    #pragma unroll
    for (int mi = 0; mi < 4; mi++) {
        #pragma unroll
        for (int half = 0; half < 2; half++) {
            int ml = wm * 64 + mi * 16 + g + half * 8;
            if (ml < nval) {
                float* orow = out + (size_t)sPerm[ml] * C_OUT + by * TILE_N + wn * 32;
                #pragma unroll
                for (int ni = 0; ni < 4; ni++) {
                    float2 v;
                    v.x = acc[mi][ni][half * 2 + 0] + bv[ni].x;
                    v.y = acc[mi][ni][half * 2 + 1] + bv[ni].y;
                    *(float2*)(orow + ni * 8 + a2) = v;
                }
            }
        }
    }
}

// ---------------------------------------------------------------------------
extern "C" void kernel_launch(void* const* d_in, const int* in_sizes, int n_in,
                              void* d_out, int out_size) {
    const float* feat   = (const float*)d_in[0];
    const float* xyz    = (const float*)d_in[1];
    const float* weight = (const float*)d_in[2];
    const float* bias   = (const float*)d_in[3];
    float* out = (float*)d_out;

    const int P = in_sizes[0] / C_IN;

    cudaFuncSetAttribute(gemm_mma_kernel,
                         cudaFuncAttributeMaxDynamicSharedMemorySize, SMEM_TOTAL);

    reset_kernel<<<1, 32>>>();
    classify_kernel<<<(P + 255) / 256, 256>>>(xyz, P);
    offsets_kernel<<<1, 32>>>();
    scatter_kernel<<<(P + 255) / 256, 256>>>(P);

    const int padrows = P + NFILT * TILE_M;
    pack_feat_kernel<<<(padrows + 7) / 8, 256>>>(feat);
    pack_weight_kernel<<<(NFILT * C_OUT) / 8, 256>>>(weight);

    const int mtiles = (P + TILE_M - 1) / TILE_M + NFILT;
    dim3 grid(mtiles, C_OUT / TILE_N);
    gemm_mma_kernel<<<grid, THREADS, SMEM_TOTAL>>>(bias, out);
}